// round 16
// baseline (speedup 1.0000x reference)
#include <cuda_runtime.h>
#include <math.h>

#define NTN   65536
#define NBATCH 32
#define NPERG 2048
#define NFEAT 128
#define NCLS  10
#define NEGV  (-1e9f)
#define MASKV (-1e30f)
#define ETOTMAX (NTN * 16 + NTN)   // 1,114,112 edges incl self loops
#define NLIVE1 (NTN / 2)           // live nodes after pool1 (exactly half)

// ---------------- scratch (device globals; no allocation allowed) ----------
__device__ float  g_h [NTN * 48];      // per-conv linear output (max HC=48)
__device__ float  g_oa[NTN * 48];      // ping buffer
__device__ float  g_ob[NTN * 48];      // pong buffer
__device__ float4 g_alsv[NTN];         // src logits, heads in .x/.y/.z (MASKV = masked)
__device__ float  g_ald[NTN * 3];      // dst logits
__device__ float  g_score[NTN];        // topk raw scores
__device__ int    g_nmask[NTN];        // node mask
__device__ int    g_live[NTN];         // compacted live-node list (pool1)
__device__ float  g_psum [128 * NFEAT];  // BN partial sums
__device__ float  g_psq  [128 * NFEAT];
__device__ float  g_bnc  [2 * NFEAT];    // BN affine: scale[0:128], shift[128:256]
// CSR (built once per launch)
__device__ int g_deg [NTN];
__device__ int g_off [NTN + 1];
__device__ int g_cur [NTN];
__device__ int g_bsum[256];
__device__ int g_csrc[ETOTMAX];

__device__ __forceinline__ float lrelu(float v) { return v > 0.f ? v : 0.2f * v; }

// ---------------- BN partial stats + zero degrees + mask init ----------------
__global__ void k_stats(const float* __restrict__ x) {
    int f = threadIdx.x;                       // 128 threads
    int b = blockIdx.x;                        // 128 blocks
    int r0 = b * (NTN / 128);
    float s = 0.f, s2 = 0.f;
    for (int r = r0; r < r0 + NTN / 128; ++r) {
        float v = x[r * NFEAT + f];
        s += v; s2 += v * v;
    }
    g_psum[b * NFEAT + f] = s;
    g_psq [b * NFEAT + f] = s2;
    int gid = b * 128 + f;
    for (int i = gid; i < NTN; i += 128 * 128) { g_deg[i] = 0; g_nmask[i] = 1; }
}

// ---------------- degree count + BN coefficient reduce (fused) -------------
__global__ void k_deg_bnc(const int* __restrict__ dst, int E, int Etot,
                          const float* __restrict__ gamma, const float* __restrict__ beta) {
    if (blockIdx.x == gridDim.x - 1) {
        int f = threadIdx.x;
        if (f < NFEAT) {
            float s = 0.f, s2 = 0.f;
            for (int b = 0; b < 128; ++b) {
                s  += g_psum[b * NFEAT + f];
                s2 += g_psq [b * NFEAT + f];
            }
            float mu  = s  * (1.f / NTN);
            float var = s2 * (1.f / NTN) - mu * mu;
            float rstd = rsqrtf(var + 1e-5f);
            float ga = gamma[f];
            g_bnc[f]         = ga * rstd;
            g_bnc[NFEAT + f] = beta[f] - mu * ga * rstd;
        }
        return;
    }
    int e = blockIdx.x * blockDim.x + threadIdx.x;
    if (e >= Etot) return;
    int d = (e < E) ? dst[e] : (e - E);
    atomicAdd(&g_deg[d], 1);
}

// ---------------- hierarchical scan of degrees ----------------
__global__ void k_scan_block() {            // 256 blocks x 256 threads
    __shared__ int sh[256];
    int n = blockIdx.x * 256 + threadIdx.x;
    int v = g_deg[n];
    sh[threadIdx.x] = v;
    __syncthreads();
    for (int o = 1; o < 256; o <<= 1) {
        int t = (threadIdx.x >= o) ? sh[threadIdx.x - o] : 0;
        __syncthreads();
        sh[threadIdx.x] += t;
        __syncthreads();
    }
    g_off[n] = sh[threadIdx.x] - v;
    if (threadIdx.x == 255) g_bsum[blockIdx.x] = sh[255];
}

__global__ void k_scan_add2(int Etot) {     // 256 blocks x 256 threads
    __shared__ int sh[256];
    int t = threadIdx.x;
    sh[t] = g_bsum[t];
    __syncthreads();
    for (int o = 1; o < 256; o <<= 1) {
        int v = (t >= o) ? sh[t - o] : 0;
        __syncthreads();
        sh[t] += v;
        __syncthreads();
    }
    int bsex = (blockIdx.x > 0) ? sh[blockIdx.x - 1] : 0;   // broadcast read
    int n = blockIdx.x * 256 + t;
    int o2 = g_off[n] + bsex;
    g_off[n] = o2;
    g_cur[n] = o2;
    if (n == 0) g_off[NTN] = Etot;
}

// ---------------- scatter edges into CSR ----------------
__global__ void k_scatter(const int* __restrict__ src, const int* __restrict__ dst,
                          int E, int Etot) {
    int e = blockIdx.x * blockDim.x + threadIdx.x;
    if (e >= Etot) return;
    int s, d;
    if (e < E) { s = src[e]; d = dst[e]; } else { s = e - E; d = s; }
    int pos = atomicAdd(&g_cur[d], 1);
    g_csrc[pos] = s;
}

// ---------------- fused (BN +) linear + attention logits ----------------
// IDX: rows indirected through g_live (post-pool convs run live rows only).
template <int Fin, int H, int C, int RW, bool BNF, bool IDX>
__global__ __launch_bounds__(256) void k_lin(const float* __restrict__ xin,
                                             const float* __restrict__ W,
                                             const float* __restrict__ a_s,
                                             const float* __restrict__ a_d,
                                             float* __restrict__ h) {
    constexpr int HC = H * C;
    constexpr int FV = Fin / 4;
    __shared__ float Ws[Fin * HC];
    __shared__ float xs[8][RW * Fin];
    __shared__ float asv[HC], adv[HC];
    __shared__ float sg[BNF ? NFEAT : 1], sb[BNF ? NFEAT : 1];
    int tid = threadIdx.x, lane = tid & 31, wid = tid >> 5;
    for (int i = tid; i < Fin * HC; i += 256) Ws[i] = W[i];
    if (tid < HC) { asv[tid] = a_s[tid]; adv[tid] = a_d[tid]; }
    if (BNF && tid < NFEAT) {
        sg[tid] = g_bnc[tid];
        sb[tid] = g_bnc[NFEAT + tid];
    }
    __syncthreads();

    int rbase = (blockIdx.x * 8 + wid) * RW;
    int c0 = 2 * lane;
    bool act = (c0 < HC);

    // cooperative load of RW rows (+ BN affine for conv1)
    float4* xs4 = (float4*)xs[wid];
    for (int t = lane; t < RW * FV; t += 32) {
        int r = t / FV, off = t - r * FV;
        int row = IDX ? g_live[rbase + r] : (rbase + r);
        float4 v = ((const float4*)(xin + (size_t)row * Fin))[off];
        if (BNF) {
            int f0 = (off * 4) & (Fin - 1);
            v.x = v.x * sg[f0]     + sb[f0];
            v.y = v.y * sg[f0 + 1] + sb[f0 + 1];
            v.z = v.z * sg[f0 + 2] + sb[f0 + 2];
            v.w = v.w * sg[f0 + 3] + sb[f0 + 3];
        }
        xs4[t] = v;
    }
    __syncwarp();

    float ax[RW], ay[RW];
    #pragma unroll
    for (int r = 0; r < RW; ++r) { ax[r] = 0.f; ay[r] = 0.f; }

    if (act) {
        #pragma unroll 4
        for (int i0 = 0; i0 < Fin; i0 += 4) {
            float2 w0 = *(const float2*)&Ws[(i0 + 0) * HC + c0];
            float2 w1 = *(const float2*)&Ws[(i0 + 1) * HC + c0];
            float2 w2 = *(const float2*)&Ws[(i0 + 2) * HC + c0];
            float2 w3 = *(const float2*)&Ws[(i0 + 3) * HC + c0];
            #pragma unroll
            for (int r = 0; r < RW; ++r) {
                float4 xv = *(const float4*)&xs[wid][r * Fin + i0];
                ax[r] += xv.x * w0.x; ay[r] += xv.x * w0.y;
                ax[r] += xv.y * w1.x; ay[r] += xv.y * w1.y;
                ax[r] += xv.z * w2.x; ay[r] += xv.z * w2.y;
                ax[r] += xv.w * w3.x; ay[r] += xv.w * w3.y;
            }
        }
        #pragma unroll
        for (int r = 0; r < RW; ++r) {
            int row = IDX ? g_live[rbase + r] : (rbase + r);
            *(float2*)(h + (size_t)row * HC + c0) = make_float2(ax[r], ay[r]);
        }
    }

    #pragma unroll
    for (int r = 0; r < RW; ++r) {
        float ps = 0.f, pd = 0.f;
        if (act) {
            ps = ax[r] * asv[c0] + ay[r] * asv[c0 + 1];
            pd = ax[r] * adv[c0] + ay[r] * adv[c0 + 1];
        }
        if (C == 16) {
            #pragma unroll
            for (int o = 4; o; o >>= 1) {
                ps += __shfl_xor_sync(0xffffffffu, ps, o);
                pd += __shfl_xor_sync(0xffffffffu, pd, o);
            }
        } else {
            #pragma unroll
            for (int o = 16; o; o >>= 1) {
                ps += __shfl_xor_sync(0xffffffffu, ps, o);
                pd += __shfl_xor_sync(0xffffffffu, pd, o);
            }
        }
        float p1 = __shfl_sync(0xffffffffu, ps, 8);
        float p2 = __shfl_sync(0xffffffffu, ps, 16);
        float d1 = __shfl_sync(0xffffffffu, pd, 8);
        float d2 = __shfl_sync(0xffffffffu, pd, 16);
        if (lane == 0) {
            int rr = IDX ? g_live[rbase + r] : (rbase + r);
            int msk = IDX ? 1 : g_nmask[rr];
            if (H == 3) {
                g_alsv[rr] = msk ? make_float4(ps, p1, p2, 0.f)
                                 : make_float4(MASKV, MASKV, MASKV, 0.f);
                g_ald[rr * 3]     = pd;
                g_ald[rr * 3 + 1] = d1;
                g_ald[rr * 3 + 2] = d2;
            } else if (H == 2) {
                g_alsv[rr] = msk ? make_float4(ps, p1, 0.f, 0.f)
                                 : make_float4(MASKV, MASKV, 0.f, 0.f);
                g_ald[rr * 3]     = pd;
                g_ald[rr * 3 + 1] = d1;
            } else {
                g_alsv[rr] = msk ? make_float4(ps, 0.f, 0.f, 0.f)
                                 : make_float4(MASKV, 0.f, 0.f, 0.f);
                g_ald[rr * 3] = pd;
            }
        }
    }
}

// ---------------- fused attention softmax + aggregation ----------------
// warp per dst node (direct or via live list). Deferred-normalization softmax.
// MASKED: src may be dead -> ballot-compacted ex list.
// LIVE:   dsts come from g_live (all live; no dst-mask check).
template <int H, int C, bool MASKED, int NG, bool LIVE>
__global__ __launch_bounds__(256) void k_gat(const float* __restrict__ h,
                                             const float* __restrict__ b,
                                             float* __restrict__ out) {
    constexpr int HC = H * C;
    constexpr int CAP = 64;
    constexpr int GSZ = 32 / NG;
    __shared__ float sAl[8][CAP * H + 1];
    __shared__ int   sSr[8][CAP + 1];
    __shared__ float sAc[MASKED ? 8 : 1][MASKED ? (CAP * H + 1) : 1];
    __shared__ int   sSc[MASKED ? 8 : 1][MASKED ? (CAP + 1) : 1];
    int widx = (blockIdx.x * blockDim.x + threadIdx.x) >> 5;
    if (!LIVE && widx >= NTN) return;
    int d = LIVE ? g_live[widx] : widx;
    int lane = threadIdx.x & 31;
    int wid = (threadIdx.x >> 5) & 7;
    int grp = lane / GSZ;
    int lc  = lane & (GSZ - 1);
    int c0 = 2 * lc;
    bool act = (c0 < HC);
    bool wlane = (grp == 0) && act;

    if (!LIVE && MASKED && !g_nmask[d]) {
        if (wlane) *(float2*)(out + (size_t)d * HC + c0) = make_float2(b[c0], b[c0 + 1]);
        return;
    }

    int beg = g_off[d], end = g_off[d + 1];
    float ald_d[H], m[H];
    #pragma unroll
    for (int hh = 0; hh < H; ++hh) {
        ald_d[hh] = g_ald[d * 3 + hh];
        m[hh] = NEGV;
    }

    // phase A: gather logits, cache to smem, track max
    for (int i = beg + lane; i < end; i += 32) {
        int j = i - beg;
        int s = g_csrc[i];
        float4 av = g_alsv[s];
        float avh[3] = {av.x, av.y, av.z};
        if (j < CAP) sSr[wid][j] = s;
        #pragma unroll
        for (int hh = 0; hh < H; ++hh) {
            float v = lrelu(avh[hh] + ald_d[hh]);
            if (j < CAP) sAl[wid][j * H + hh] = v;
            m[hh] = fmaxf(m[hh], v);
        }
    }
    #pragma unroll
    for (int o = 16; o; o >>= 1) {
        #pragma unroll
        for (int hh = 0; hh < H; ++hh)
            m[hh] = fmaxf(m[hh], __shfl_xor_sync(0xffffffffu, m[hh], o));
    }

    int deg = end - beg;
    int cap = deg < CAP ? deg : CAP;
    int nk;
    float den[H];
    #pragma unroll
    for (int hh = 0; hh < H; ++hh) den[hh] = 0.f;

    if (MASKED) {
        nk = 0;
        for (int j0 = 0; j0 < cap; j0 += 32) {
            int j = j0 + lane;
            bool have = (j < cap);
            float exH[H]; int s = 0;
            bool keep = false;
            if (have) {
                s = sSr[wid][j];
                #pragma unroll
                for (int hh = 0; hh < H; ++hh) {
                    float ex = __expf(sAl[wid][j * H + hh] - m[hh]);
                    exH[hh] = ex;
                    den[hh] += ex;
                    keep = keep || (ex > 0.f);
                }
            }
            unsigned bal = __ballot_sync(0xffffffffu, keep);
            int pos = nk + __popc(bal & ((1u << lane) - 1u));
            if (keep) {
                sSc[wid][pos] = s;
                #pragma unroll
                for (int hh = 0; hh < H; ++hh) sAc[wid][pos * H + hh] = exH[hh];
            }
            nk += __popc(bal);
        }
    } else {
        for (int j = lane; j < cap; j += 32) {
            #pragma unroll
            for (int hh = 0; hh < H; ++hh) {
                float ex = __expf(sAl[wid][j * H + hh] - m[hh]);
                sAl[wid][j * H + hh] = ex;
                den[hh] += ex;
            }
        }
        nk = cap;
    }
    for (int i = beg + CAP + lane; i < end; i += 32) {
        int s = g_csrc[i];
        float4 av = g_alsv[s];
        float avh[3] = {av.x, av.y, av.z};
        #pragma unroll
        for (int hh = 0; hh < H; ++hh)
            den[hh] += __expf(lrelu(avh[hh] + ald_d[hh]) - m[hh]);
    }
    #pragma unroll
    for (int o = 16; o; o >>= 1) {
        #pragma unroll
        for (int hh = 0; hh < H; ++hh)
            den[hh] += __shfl_xor_sync(0xffffffffu, den[hh], o);
    }
    __syncwarp();

    int hh0 = c0 / C;
    float m_my = m[0], den_my = den[0];
    #pragma unroll
    for (int hh = 1; hh < H; ++hh)
        if (hh == hh0) { m_my = m[hh]; den_my = den[hh]; }
    float inv_my = 1.f / fmaxf(den_my, 1e-16f);
    float ald_my = ald_d[0];
    #pragma unroll
    for (int hh = 1; hh < H; ++hh)
        if (hh == hh0) ald_my = ald_d[hh];

    float accx = 0.f, accy = 0.f;
    if (act) {
        #pragma unroll 8
        for (int j = grp; j < nk; j += NG) {
            float a = MASKED ? sAc[wid][j * H + hh0] : sAl[wid][j * H + hh0];
            int s = MASKED ? sSc[wid][j] : sSr[wid][j];
            float2 hv = *(const float2*)(h + (size_t)s * HC + c0);
            accx += a * hv.x;
            accy += a * hv.y;
        }
    }
    for (int i = beg + CAP + grp; i < end; i += NG) {
        int s = g_csrc[i];
        float4 av = g_alsv[s];
        float avh[3] = {av.x, av.y, av.z};
        float a = __expf(lrelu(avh[hh0] + ald_my) - m_my);
        if (a > 0.f && act) {
            float2 hv = *(const float2*)(h + (size_t)s * HC + c0);
            accx += a * hv.x;
            accy += a * hv.y;
        }
    }
    #pragma unroll
    for (int o = GSZ; o < 32; o <<= 1) {
        accx += __shfl_xor_sync(0xffffffffu, accx, o);
        accy += __shfl_xor_sync(0xffffffffu, accy, o);
    }
    if (wlane) *(float2*)(out + (size_t)d * HC + c0) =
        make_float2(accx * inv_my + b[c0], accy * inv_my + b[c0 + 1]);
}

// ---------------- TopK pooling (float2-vectorized; F even) ----------------
// do_live: also emit compacted live list + MASKV alsv sentinel for dropped.
__global__ void k_topk(float* __restrict__ x, const float* __restrict__ p,
                       int F, int kkeep, int do_live) {
    __shared__ float ss[NPERG];
    __shared__ int   wsum[32];
    __shared__ int   wsex[32];
    __shared__ float s_thr;
    __shared__ int   s_need;
    int g = blockIdx.x;
    int base = g * NPERG;
    int tid = threadIdx.x;
    int lane = tid & 31, wid = tid >> 5;
    int F2 = F >> 1;
    const float2* p2 = (const float2*)p;

    float nrm = 0.f;
    for (int i = 0; i < F2; ++i) { float2 pv = p2[i]; nrm += pv.x * pv.x + pv.y * pv.y; }
    nrm = rsqrtf(nrm);

    for (int n = tid; n < NPERG; n += blockDim.x) {
        int node = base + n;
        const float2* xr = (const float2*)(x + (size_t)node * F);
        float sc = 0.f;
        for (int i = 0; i < F2; ++i) {
            float2 xv = xr[i], pv = p2[i];
            sc += xv.x * pv.x + xv.y * pv.y;
        }
        sc *= nrm;
        g_score[node] = sc;
        ss[n] = g_nmask[node] ? sc : NEGV;
    }
    __syncthreads();

    for (int kk = 2; kk <= NPERG; kk <<= 1) {
        for (int j = kk >> 1; j > 0; j >>= 1) {
            for (int i = tid; i < NPERG; i += blockDim.x) {
                int ixj = i ^ j;
                if (ixj > i) {
                    float a = ss[i], bb = ss[ixj];
                    bool up = ((i & kk) == 0);
                    if ((a > bb) == up) { ss[i] = bb; ss[ixj] = a; }
                }
            }
            __syncthreads();
        }
    }

    if (tid == 0) {
        float thr = ss[NPERG - kkeep];
        int lo = NPERG - kkeep, hi = NPERG;
        while (lo < hi) {
            int mid = (lo + hi) >> 1;
            if (ss[mid] > thr) hi = mid; else lo = mid + 1;
        }
        s_thr = thr;
        s_need = kkeep - (NPERG - lo);
    }
    __syncthreads();
    float thr = s_thr;
    int need_eq = s_need;

    int n0 = tid * 2, n1 = n0 + 1;
    float sc0 = g_nmask[base + n0] ? g_score[base + n0] : NEGV;
    float sc1 = g_nmask[base + n1] ? g_score[base + n1] : NEGV;
    int f0 = (sc0 == thr) ? 1 : 0;
    int f1 = (sc1 == thr) ? 1 : 0;
    int lsum = f0 + f1;
    int incl = lsum;
    #pragma unroll
    for (int o = 1; o < 32; o <<= 1) {
        int t = __shfl_up_sync(0xffffffffu, incl, o);
        if (lane >= o) incl += t;
    }
    if (lane == 31) wsum[wid] = incl;
    __syncthreads();
    if (wid == 0) {
        int v = wsum[lane];
        int inc2 = v;
        #pragma unroll
        for (int o = 1; o < 32; o <<= 1) {
            int t = __shfl_up_sync(0xffffffffu, inc2, o);
            if (lane >= o) inc2 += t;
        }
        wsex[lane] = inc2 - v;
    }
    __syncthreads();
    int rank0 = wsex[wid] + (incl - lsum);
    int rank1 = rank0 + f0;

    int keep0 = (sc0 > thr) || (f0 && rank0 < need_eq);
    int keep1 = (sc1 > thr) || (f1 && rank1 < need_eq);

    // second scan: compact kept nodes into g_live (node order)
    if (do_live) {
        int ksum = keep0 + keep1;
        int kincl = ksum;
        #pragma unroll
        for (int o = 1; o < 32; o <<= 1) {
            int t = __shfl_up_sync(0xffffffffu, kincl, o);
            if (lane >= o) kincl += t;
        }
        __syncthreads();              // everyone done reading wsex from scan 1
        if (lane == 31) wsum[wid] = kincl;
        __syncthreads();
        if (wid == 0) {
            int v = wsum[lane];
            int inc2 = v;
            #pragma unroll
            for (int o = 1; o < 32; o <<= 1) {
                int t = __shfl_up_sync(0xffffffffu, inc2, o);
                if (lane >= o) inc2 += t;
            }
            wsex[lane] = inc2 - v;
        }
        __syncthreads();
        int kr0 = wsex[wid] + (kincl - ksum);
        int kr1 = kr0 + keep0;
        if (keep0) g_live[g * kkeep + kr0] = base + n0;
        else       g_alsv[base + n0] = make_float4(MASKV, MASKV, MASKV, 0.f);
        if (keep1) g_live[g * kkeep + kr1] = base + n1;
        else       g_alsv[base + n1] = make_float4(MASKV, MASKV, MASKV, 0.f);
    }

    g_nmask[base + n0] = keep0;
    g_nmask[base + n1] = keep1;
    float t0 = keep0 ? tanhf(g_score[base + n0]) : 0.f;
    float t1 = keep1 ? tanhf(g_score[base + n1]) : 0.f;
    float2* xr0 = (float2*)(x + (size_t)(base + n0) * F);
    float2* xr1 = (float2*)(x + (size_t)(base + n1) * F);
    for (int i = 0; i < F2; ++i) { float2 v = xr0[i]; v.x *= t0; v.y *= t0; xr0[i] = v; }
    for (int i = 0; i < F2; ++i) { float2 v = xr1[i]; v.x *= t1; v.y *= t1; xr1[i] = v; }
}

// ---------------- final mean + log_softmax ----------------
__global__ void k_final(const float* __restrict__ x, float* __restrict__ out) {
    __shared__ float red[NCLS][9];
    int g = blockIdx.x;
    int base = g * NPERG;
    float acc[NCLS];
    for (int c = 0; c < NCLS; ++c) acc[c] = 0.f;
    for (int n = threadIdx.x; n < NPERG; n += blockDim.x) {
        const float2* xr = (const float2*)(x + (size_t)(base + n) * NCLS);
        #pragma unroll
        for (int c = 0; c < NCLS / 2; ++c) {
            float2 v = xr[c];
            acc[2 * c] += v.x;
            acc[2 * c + 1] += v.y;
        }
    }
    for (int off = 16; off; off >>= 1)
        for (int c = 0; c < NCLS; ++c)
            acc[c] += __shfl_down_sync(0xffffffffu, acc[c], off);
    int lane = threadIdx.x & 31, wid = threadIdx.x >> 5;
    if (lane == 0)
        for (int c = 0; c < NCLS; ++c) red[c][wid] = acc[c];
    __syncthreads();
    if (threadIdx.x == 0) {
        int nw = blockDim.x / 32;
        float z[NCLS];
        for (int c = 0; c < NCLS; ++c) {
            float s = 0.f;
            for (int w = 0; w < nw; ++w) s += red[c][w];
            z[c] = s * (1.f / (NPERG / 4));
        }
        float mx = z[0];
        for (int c = 1; c < NCLS; ++c) mx = fmaxf(mx, z[c]);
        float se = 0.f;
        for (int c = 0; c < NCLS; ++c) se += expf(z[c] - mx);
        float lse = logf(se) + mx;
        for (int c = 0; c < NCLS; ++c) out[g * NCLS + c] = z[c] - lse;
    }
}

// ---------------- host orchestration ----------------
extern "C" void kernel_launch(void* const* d_in, const int* in_sizes, int n_in,
                              void* d_out, int out_size) {
    const float* x     = (const float*)d_in[0];
    const int*   ei    = (const int*)  d_in[1];
    const float* gamma = (const float*)d_in[3];
    const float* beta  = (const float*)d_in[4];
    const float* W1  = (const float*)d_in[5];
    const float* as1 = (const float*)d_in[6];
    const float* ad1 = (const float*)d_in[7];
    const float* b1  = (const float*)d_in[8];
    const float* W2  = (const float*)d_in[9];
    const float* as2 = (const float*)d_in[10];
    const float* ad2 = (const float*)d_in[11];
    const float* b2  = (const float*)d_in[12];
    const float* W3  = (const float*)d_in[13];
    const float* as3 = (const float*)d_in[14];
    const float* ad3 = (const float*)d_in[15];
    const float* b3  = (const float*)d_in[16];
    const float* W4  = (const float*)d_in[17];
    const float* as4 = (const float*)d_in[18];
    const float* ad4 = (const float*)d_in[19];
    const float* b4  = (const float*)d_in[20];
    const float* p1  = (const float*)d_in[21];
    const float* p2  = (const float*)d_in[22];

    int E = in_sizes[1] / 2;
    const int* src = ei;
    const int* dst = ei + E;
    int Etot = E + NTN;
    int eb = (Etot + 255) / 256;

    float *h, *oa, *ob;
    cudaGetSymbolAddress((void**)&h,  g_h);
    cudaGetSymbolAddress((void**)&oa, g_oa);
    cudaGetSymbolAddress((void**)&ob, g_ob);

    int lingrid4 = NTN / 32;            // conv1: warp per 4 rows
    int lingrid8 = NTN / 64;            // conv2: warp per 8 rows
    int lingridL = NLIVE1 / 64;         // conv3/4: live rows, warp per 8
    int gatgrid  = NTN * 32 / 256;      // warp per dst node (all nodes)
    int gatgridL = NLIVE1 * 32 / 256;   // warp per LIVE dst node

    k_stats<<<128, 128>>>(x);                                      // 0
    k_deg_bnc<<<eb + 1, 256>>>(dst, E, Etot, gamma, beta);         // 1
    k_scan_block<<<256, 256>>>();                                  // 2
    k_lin<NFEAT, 3, 16, 4, true, false><<<lingrid4, 256>>>(x, W1, as1, ad1, h); // 3 <- ncu
    k_scan_add2<<<256, 256>>>(Etot);                               // 4
    k_scatter<<<eb, 256>>>(src, dst, E, Etot);                     // 5
    k_gat<3, 16, false, 1, false><<<gatgrid, 256>>>(h, b1, oa);    // 6

    k_lin<48, 3, 16, 8, false, false><<<lingrid8, 256>>>(oa, W2, as2, ad2, h);
    k_gat<3, 16, false, 1, false><<<gatgrid, 256>>>(h, b2, ob);
    k_topk<<<NBATCH, 1024>>>(ob, p1, 48, NPERG / 2, 1);            // emits g_live
    k_lin<48, 2, 16, 8, false, true><<<lingridL, 256>>>(ob, W3, as3, ad3, h);
    k_gat<2, 16, true, 2, true><<<gatgridL, 256>>>(h, b3, oa);
    k_lin<32, 1, 10, 8, false, true><<<lingridL, 256>>>(oa, W4, as4, ad4, h);
    k_gat<1, 10, true, 4, true><<<gatgridL, 256>>>(h, b4, ob);
    k_topk<<<NBATCH, 1024>>>(ob, p2, 10, NPERG / 4, 0);
    k_final<<<NBATCH, 256>>>(ob, (float*)d_out);
}

// round 17
// speedup vs baseline: 1.0785x; 1.0785x over previous
#include <cuda_runtime.h>
#include <math.h>

#define NTN   65536
#define NBATCH 32
#define NPERG 2048
#define NFEAT 128
#define NCLS  10
#define NEGV  (-1e9f)
#define MASKV (-1e30f)
#define ETOTMAX (NTN * 16 + NTN)   // 1,114,112 edges incl self loops
#define NLIVE1 (NTN / 2)           // live nodes after pool1 (exactly half)

// ---------------- scratch (device globals; no allocation allowed) ----------
__device__ float  g_h [NTN * 48];      // per-conv linear output (max HC=48)
__device__ float  g_oa[NTN * 48];      // ping buffer
__device__ float  g_ob[NTN * 48];      // pong buffer
__device__ float4 g_alsv[NTN];         // src logits, heads in .x/.y/.z (MASKV = masked)
__device__ float  g_ald[NTN * 3];      // dst logits
__device__ float  g_score[NTN];        // topk raw scores
__device__ int    g_nmask[NTN];        // node mask
__device__ int    g_live[NTN];         // compacted live-node list (pool1)
__device__ float  g_psum [128 * NFEAT];  // BN partial sums
__device__ float  g_psq  [128 * NFEAT];
__device__ float  g_bnc  [2 * NFEAT];    // BN affine: scale[0:128], shift[128:256]
// CSR (built once per launch)
__device__ int g_deg [NTN];
__device__ int g_off [NTN + 1];
__device__ int g_cur [NTN];
__device__ int g_bsum[256];
__device__ int g_csrc[ETOTMAX];

__device__ __forceinline__ float lrelu(float v) { return v > 0.f ? v : 0.2f * v; }

// ---------------- BN partial stats + zero degrees + mask init ----------------
__global__ void k_stats(const float* __restrict__ x) {
    int f = threadIdx.x;                       // 128 threads
    int b = blockIdx.x;                        // 128 blocks
    int r0 = b * (NTN / 128);
    float s = 0.f, s2 = 0.f;
    for (int r = r0; r < r0 + NTN / 128; ++r) {
        float v = x[r * NFEAT + f];
        s += v; s2 += v * v;
    }
    g_psum[b * NFEAT + f] = s;
    g_psq [b * NFEAT + f] = s2;
    int gid = b * 128 + f;
    for (int i = gid; i < NTN; i += 128 * 128) { g_deg[i] = 0; g_nmask[i] = 1; }
}

// ---------------- degree count + BN coefficient reduce (fused) -------------
__global__ void k_deg_bnc(const int* __restrict__ dst, int E, int Etot,
                          const float* __restrict__ gamma, const float* __restrict__ beta) {
    if (blockIdx.x == gridDim.x - 1) {
        int f = threadIdx.x;
        if (f < NFEAT) {
            float s = 0.f, s2 = 0.f;
            for (int b = 0; b < 128; ++b) {
                s  += g_psum[b * NFEAT + f];
                s2 += g_psq [b * NFEAT + f];
            }
            float mu  = s  * (1.f / NTN);
            float var = s2 * (1.f / NTN) - mu * mu;
            float rstd = rsqrtf(var + 1e-5f);
            float ga = gamma[f];
            g_bnc[f]         = ga * rstd;
            g_bnc[NFEAT + f] = beta[f] - mu * ga * rstd;
        }
        return;
    }
    int e = blockIdx.x * blockDim.x + threadIdx.x;
    if (e >= Etot) return;
    int d = (e < E) ? dst[e] : (e - E);
    atomicAdd(&g_deg[d], 1);
}

// ---------------- hierarchical scan of degrees ----------------
__global__ void k_scan_block() {            // 256 blocks x 256 threads
    __shared__ int sh[256];
    int n = blockIdx.x * 256 + threadIdx.x;
    int v = g_deg[n];
    sh[threadIdx.x] = v;
    __syncthreads();
    for (int o = 1; o < 256; o <<= 1) {
        int t = (threadIdx.x >= o) ? sh[threadIdx.x - o] : 0;
        __syncthreads();
        sh[threadIdx.x] += t;
        __syncthreads();
    }
    g_off[n] = sh[threadIdx.x] - v;
    if (threadIdx.x == 255) g_bsum[blockIdx.x] = sh[255];
}

__global__ void k_scan_add2(int Etot) {     // 256 blocks x 256 threads
    __shared__ int sh[256];
    int t = threadIdx.x;
    sh[t] = g_bsum[t];
    __syncthreads();
    for (int o = 1; o < 256; o <<= 1) {
        int v = (t >= o) ? sh[t - o] : 0;
        __syncthreads();
        sh[t] += v;
        __syncthreads();
    }
    int bsex = (blockIdx.x > 0) ? sh[blockIdx.x - 1] : 0;   // broadcast read
    int n = blockIdx.x * 256 + t;
    int o2 = g_off[n] + bsex;
    g_off[n] = o2;
    g_cur[n] = o2;
    if (n == 0) g_off[NTN] = Etot;
}

// ---------------- scatter edges into CSR ----------------
__global__ void k_scatter(const int* __restrict__ src, const int* __restrict__ dst,
                          int E, int Etot) {
    int e = blockIdx.x * blockDim.x + threadIdx.x;
    if (e >= Etot) return;
    int s, d;
    if (e < E) { s = src[e]; d = dst[e]; } else { s = e - E; d = s; }
    int pos = atomicAdd(&g_cur[d], 1);
    g_csrc[pos] = s;
}

// ---------------- fused (BN +) linear + attention logits ----------------
// IDX: rows indirected through g_live (post-pool convs run live rows only).
template <int Fin, int H, int C, int RW, bool BNF, bool IDX>
__global__ __launch_bounds__(256) void k_lin(const float* __restrict__ xin,
                                             const float* __restrict__ W,
                                             const float* __restrict__ a_s,
                                             const float* __restrict__ a_d,
                                             float* __restrict__ h) {
    constexpr int HC = H * C;
    constexpr int FV = Fin / 4;
    __shared__ float Ws[Fin * HC];
    __shared__ float xs[8][RW * Fin];
    __shared__ float asv[HC], adv[HC];
    __shared__ float sg[BNF ? NFEAT : 1], sb[BNF ? NFEAT : 1];
    int tid = threadIdx.x, lane = tid & 31, wid = tid >> 5;
    for (int i = tid; i < Fin * HC; i += 256) Ws[i] = W[i];
    if (tid < HC) { asv[tid] = a_s[tid]; adv[tid] = a_d[tid]; }
    if (BNF && tid < NFEAT) {
        sg[tid] = g_bnc[tid];
        sb[tid] = g_bnc[NFEAT + tid];
    }
    __syncthreads();

    int rbase = (blockIdx.x * 8 + wid) * RW;
    int c0 = 2 * lane;
    bool act = (c0 < HC);

    float4* xs4 = (float4*)xs[wid];
    for (int t = lane; t < RW * FV; t += 32) {
        int r = t / FV, off = t - r * FV;
        int row = IDX ? g_live[rbase + r] : (rbase + r);
        float4 v = ((const float4*)(xin + (size_t)row * Fin))[off];
        if (BNF) {
            int f0 = (off * 4) & (Fin - 1);
            v.x = v.x * sg[f0]     + sb[f0];
            v.y = v.y * sg[f0 + 1] + sb[f0 + 1];
            v.z = v.z * sg[f0 + 2] + sb[f0 + 2];
            v.w = v.w * sg[f0 + 3] + sb[f0 + 3];
        }
        xs4[t] = v;
    }
    __syncwarp();

    float ax[RW], ay[RW];
    #pragma unroll
    for (int r = 0; r < RW; ++r) { ax[r] = 0.f; ay[r] = 0.f; }

    if (act) {
        #pragma unroll 4
        for (int i0 = 0; i0 < Fin; i0 += 4) {
            float2 w0 = *(const float2*)&Ws[(i0 + 0) * HC + c0];
            float2 w1 = *(const float2*)&Ws[(i0 + 1) * HC + c0];
            float2 w2 = *(const float2*)&Ws[(i0 + 2) * HC + c0];
            float2 w3 = *(const float2*)&Ws[(i0 + 3) * HC + c0];
            #pragma unroll
            for (int r = 0; r < RW; ++r) {
                float4 xv = *(const float4*)&xs[wid][r * Fin + i0];
                ax[r] += xv.x * w0.x; ay[r] += xv.x * w0.y;
                ax[r] += xv.y * w1.x; ay[r] += xv.y * w1.y;
                ax[r] += xv.z * w2.x; ay[r] += xv.z * w2.y;
                ax[r] += xv.w * w3.x; ay[r] += xv.w * w3.y;
            }
        }
        #pragma unroll
        for (int r = 0; r < RW; ++r) {
            int row = IDX ? g_live[rbase + r] : (rbase + r);
            *(float2*)(h + (size_t)row * HC + c0) = make_float2(ax[r], ay[r]);
        }
    }

    #pragma unroll
    for (int r = 0; r < RW; ++r) {
        float ps = 0.f, pd = 0.f;
        if (act) {
            ps = ax[r] * asv[c0] + ay[r] * asv[c0 + 1];
            pd = ax[r] * adv[c0] + ay[r] * adv[c0 + 1];
        }
        if (C == 16) {
            #pragma unroll
            for (int o = 4; o; o >>= 1) {
                ps += __shfl_xor_sync(0xffffffffu, ps, o);
                pd += __shfl_xor_sync(0xffffffffu, pd, o);
            }
        } else {
            #pragma unroll
            for (int o = 16; o; o >>= 1) {
                ps += __shfl_xor_sync(0xffffffffu, ps, o);
                pd += __shfl_xor_sync(0xffffffffu, pd, o);
            }
        }
        float p1 = __shfl_sync(0xffffffffu, ps, 8);
        float p2 = __shfl_sync(0xffffffffu, ps, 16);
        float d1 = __shfl_sync(0xffffffffu, pd, 8);
        float d2 = __shfl_sync(0xffffffffu, pd, 16);
        if (lane == 0) {
            int rr = IDX ? g_live[rbase + r] : (rbase + r);
            int msk = IDX ? 1 : g_nmask[rr];
            if (H == 3) {
                g_alsv[rr] = msk ? make_float4(ps, p1, p2, 0.f)
                                 : make_float4(MASKV, MASKV, MASKV, 0.f);
                g_ald[rr * 3]     = pd;
                g_ald[rr * 3 + 1] = d1;
                g_ald[rr * 3 + 2] = d2;
            } else if (H == 2) {
                g_alsv[rr] = msk ? make_float4(ps, p1, 0.f, 0.f)
                                 : make_float4(MASKV, MASKV, 0.f, 0.f);
                g_ald[rr * 3]     = pd;
                g_ald[rr * 3 + 1] = d1;
            } else {
                g_alsv[rr] = msk ? make_float4(ps, 0.f, 0.f, 0.f)
                                 : make_float4(MASKV, 0.f, 0.f, 0.f);
                g_ald[rr * 3] = pd;
            }
        }
    }
}

// ---------------- fused attention softmax + aggregation ----------------
template <int H, int C, bool MASKED, int NG, bool LIVE>
__global__ __launch_bounds__(256) void k_gat(const float* __restrict__ h,
                                             const float* __restrict__ b,
                                             float* __restrict__ out) {
    constexpr int HC = H * C;
    constexpr int CAP = 64;
    constexpr int GSZ = 32 / NG;
    __shared__ float sAl[8][CAP * H + 1];
    __shared__ int   sSr[8][CAP + 1];
    __shared__ float sAc[MASKED ? 8 : 1][MASKED ? (CAP * H + 1) : 1];
    __shared__ int   sSc[MASKED ? 8 : 1][MASKED ? (CAP + 1) : 1];
    int widx = (blockIdx.x * blockDim.x + threadIdx.x) >> 5;
    if (!LIVE && widx >= NTN) return;
    int d = LIVE ? g_live[widx] : widx;
    int lane = threadIdx.x & 31;
    int wid = (threadIdx.x >> 5) & 7;
    int grp = lane / GSZ;
    int lc  = lane & (GSZ - 1);
    int c0 = 2 * lc;
    bool act = (c0 < HC);
    bool wlane = (grp == 0) && act;

    if (!LIVE && MASKED && !g_nmask[d]) {
        if (wlane) *(float2*)(out + (size_t)d * HC + c0) = make_float2(b[c0], b[c0 + 1]);
        return;
    }

    int beg = g_off[d], end = g_off[d + 1];
    float ald_d[H], m[H];
    #pragma unroll
    for (int hh = 0; hh < H; ++hh) {
        ald_d[hh] = g_ald[d * 3 + hh];
        m[hh] = NEGV;
    }

    for (int i = beg + lane; i < end; i += 32) {
        int j = i - beg;
        int s = g_csrc[i];
        float4 av = g_alsv[s];
        float avh[3] = {av.x, av.y, av.z};
        if (j < CAP) sSr[wid][j] = s;
        #pragma unroll
        for (int hh = 0; hh < H; ++hh) {
            float v = lrelu(avh[hh] + ald_d[hh]);
            if (j < CAP) sAl[wid][j * H + hh] = v;
            m[hh] = fmaxf(m[hh], v);
        }
    }
    #pragma unroll
    for (int o = 16; o; o >>= 1) {
        #pragma unroll
        for (int hh = 0; hh < H; ++hh)
            m[hh] = fmaxf(m[hh], __shfl_xor_sync(0xffffffffu, m[hh], o));
    }

    int deg = end - beg;
    int cap = deg < CAP ? deg : CAP;
    int nk;
    float den[H];
    #pragma unroll
    for (int hh = 0; hh < H; ++hh) den[hh] = 0.f;

    if (MASKED) {
        nk = 0;
        for (int j0 = 0; j0 < cap; j0 += 32) {
            int j = j0 + lane;
            bool have = (j < cap);
            float exH[H]; int s = 0;
            bool keep = false;
            if (have) {
                s = sSr[wid][j];
                #pragma unroll
                for (int hh = 0; hh < H; ++hh) {
                    float ex = __expf(sAl[wid][j * H + hh] - m[hh]);
                    exH[hh] = ex;
                    den[hh] += ex;
                    keep = keep || (ex > 0.f);
                }
            }
            unsigned bal = __ballot_sync(0xffffffffu, keep);
            int pos = nk + __popc(bal & ((1u << lane) - 1u));
            if (keep) {
                sSc[wid][pos] = s;
                #pragma unroll
                for (int hh = 0; hh < H; ++hh) sAc[wid][pos * H + hh] = exH[hh];
            }
            nk += __popc(bal);
        }
    } else {
        for (int j = lane; j < cap; j += 32) {
            #pragma unroll
            for (int hh = 0; hh < H; ++hh) {
                float ex = __expf(sAl[wid][j * H + hh] - m[hh]);
                sAl[wid][j * H + hh] = ex;
                den[hh] += ex;
            }
        }
        nk = cap;
    }
    for (int i = beg + CAP + lane; i < end; i += 32) {
        int s = g_csrc[i];
        float4 av = g_alsv[s];
        float avh[3] = {av.x, av.y, av.z};
        #pragma unroll
        for (int hh = 0; hh < H; ++hh)
            den[hh] += __expf(lrelu(avh[hh] + ald_d[hh]) - m[hh]);
    }
    #pragma unroll
    for (int o = 16; o; o >>= 1) {
        #pragma unroll
        for (int hh = 0; hh < H; ++hh)
            den[hh] += __shfl_xor_sync(0xffffffffu, den[hh], o);
    }
    __syncwarp();

    int hh0 = c0 / C;
    float m_my = m[0], den_my = den[0];
    #pragma unroll
    for (int hh = 1; hh < H; ++hh)
        if (hh == hh0) { m_my = m[hh]; den_my = den[hh]; }
    float inv_my = 1.f / fmaxf(den_my, 1e-16f);
    float ald_my = ald_d[0];
    #pragma unroll
    for (int hh = 1; hh < H; ++hh)
        if (hh == hh0) ald_my = ald_d[hh];

    float accx = 0.f, accy = 0.f;
    if (act) {
        #pragma unroll 8
        for (int j = grp; j < nk; j += NG) {
            float a = MASKED ? sAc[wid][j * H + hh0] : sAl[wid][j * H + hh0];
            int s = MASKED ? sSc[wid][j] : sSr[wid][j];
            float2 hv = *(const float2*)(h + (size_t)s * HC + c0);
            accx += a * hv.x;
            accy += a * hv.y;
        }
    }
    for (int i = beg + CAP + grp; i < end; i += NG) {
        int s = g_csrc[i];
        float4 av = g_alsv[s];
        float avh[3] = {av.x, av.y, av.z};
        float a = __expf(lrelu(avh[hh0] + ald_my) - m_my);
        if (a > 0.f && act) {
            float2 hv = *(const float2*)(h + (size_t)s * HC + c0);
            accx += a * hv.x;
            accy += a * hv.y;
        }
    }
    #pragma unroll
    for (int o = GSZ; o < 32; o <<= 1) {
        accx += __shfl_xor_sync(0xffffffffu, accx, o);
        accy += __shfl_xor_sync(0xffffffffu, accy, o);
    }
    if (wlane) *(float2*)(out + (size_t)d * HC + c0) =
        make_float2(accx * inv_my + b[c0], accy * inv_my + b[c0 + 1]);
}

// ---------------- TopK pooling (radix-select; float2-vectorized) -----------
// Key map: monotone float->uint bijection. Radix-select finds the exact key
// with ascending rank NPERG-kkeep (== the kkeep-th largest, same element the
// bitonic sort indexed); count(>thr) gives need_eq. Tie handling unchanged.
// DOFINAL: fuse the graph mean + log_softmax (pool2); skip dead writes.
template <bool DOFINAL>
__global__ void k_topk(float* __restrict__ x, const float* __restrict__ p,
                       int F, int kkeep, int do_live, float* __restrict__ out) {
    __shared__ unsigned keys[NPERG];
    __shared__ int  hist[256];
    __shared__ int  hscan[256];
    __shared__ int  wsum[32];
    __shared__ int  wsex[32];
    __shared__ unsigned s_prefix;
    __shared__ int  s_rank, s_bin, s_newrank, s_gt;
    __shared__ float redf[NCLS][33];
    int g = blockIdx.x;
    int base = g * NPERG;
    int tid = threadIdx.x;
    int lane = tid & 31, wid = tid >> 5;
    int F2 = F >> 1;
    const float2* p2 = (const float2*)p;

    float nrm = 0.f;
    for (int i = 0; i < F2; ++i) { float2 pv = p2[i]; nrm += pv.x * pv.x + pv.y * pv.y; }
    nrm = rsqrtf(nrm);

    for (int n = tid; n < NPERG; n += blockDim.x) {
        int node = base + n;
        const float2* xr = (const float2*)(x + (size_t)node * F);
        float sc = 0.f;
        for (int i = 0; i < F2; ++i) {
            float2 xv = xr[i], pv = p2[i];
            sc += xv.x * pv.x + xv.y * pv.y;
        }
        sc *= nrm;
        g_score[node] = sc;
        float msc = g_nmask[node] ? sc : NEGV;
        unsigned u = __float_as_uint(msc);
        keys[n] = (u & 0x80000000u) ? ~u : (u | 0x80000000u);
    }
    if (tid == 0) { s_prefix = 0; s_rank = NPERG - kkeep; s_gt = 0; }
    __syncthreads();

    // radix select, high byte to low
    for (int byte = 3; byte >= 0; --byte) {
        if (tid < 256) hist[tid] = 0;
        __syncthreads();
        unsigned pref = s_prefix;
        unsigned pmask = (byte == 3) ? 0u : (0xFFFFFFFFu << ((byte + 1) * 8));
        for (int n = tid; n < NPERG; n += blockDim.x) {
            unsigned k = keys[n];
            if ((k & pmask) == (pref & pmask))
                atomicAdd(&hist[(k >> (byte * 8)) & 255], 1);
        }
        __syncthreads();
        if (tid < 256) hscan[tid] = hist[tid];
        __syncthreads();
        for (int o = 1; o < 256; o <<= 1) {
            int v = (tid < 256 && tid >= o) ? hscan[tid - o] : 0;
            __syncthreads();
            if (tid < 256) hscan[tid] += v;
            __syncthreads();
        }
        if (tid < 256) {
            int cumI = hscan[tid];
            int cumE = cumI - hist[tid];
            if (hist[tid] > 0 && s_rank >= cumE && s_rank < cumI) {
                s_bin = tid;
                s_newrank = s_rank - cumE;
            }
        }
        __syncthreads();
        if (tid == 0) {
            s_prefix = pref | ((unsigned)s_bin << (byte * 8));
            s_rank = s_newrank;
        }
        __syncthreads();
    }
    unsigned thrkey = s_prefix;
    float thr = (thrkey & 0x80000000u) ? __uint_as_float(thrkey ^ 0x80000000u)
                                       : __uint_as_float(~thrkey);
    // count strictly greater
    int lgt = 0;
    for (int n = tid; n < NPERG; n += blockDim.x) lgt += (keys[n] > thrkey);
    #pragma unroll
    for (int o = 16; o; o >>= 1) lgt += __shfl_down_sync(0xffffffffu, lgt, o);
    if (lane == 0 && lgt) atomicAdd(&s_gt, lgt);
    __syncthreads();
    int need_eq = kkeep - s_gt;

    // per-thread 2 rows; tie rank scan (identical semantics to before)
    int n0 = tid * 2, n1 = n0 + 1;
    float sc0 = g_nmask[base + n0] ? g_score[base + n0] : NEGV;
    float sc1 = g_nmask[base + n1] ? g_score[base + n1] : NEGV;
    int f0 = (sc0 == thr) ? 1 : 0;
    int f1 = (sc1 == thr) ? 1 : 0;
    int lsum = f0 + f1;
    int incl = lsum;
    #pragma unroll
    for (int o = 1; o < 32; o <<= 1) {
        int t = __shfl_up_sync(0xffffffffu, incl, o);
        if (lane >= o) incl += t;
    }
    if (lane == 31) wsum[wid] = incl;
    __syncthreads();
    if (wid == 0) {
        int v = wsum[lane];
        int inc2 = v;
        #pragma unroll
        for (int o = 1; o < 32; o <<= 1) {
            int t = __shfl_up_sync(0xffffffffu, inc2, o);
            if (lane >= o) inc2 += t;
        }
        wsex[lane] = inc2 - v;
    }
    __syncthreads();
    int rank0 = wsex[wid] + (incl - lsum);
    int rank1 = rank0 + f0;

    int keep0 = (sc0 > thr) || (f0 && rank0 < need_eq);
    int keep1 = (sc1 > thr) || (f1 && rank1 < need_eq);

    if (do_live) {
        int ksum = keep0 + keep1;
        int kincl = ksum;
        #pragma unroll
        for (int o = 1; o < 32; o <<= 1) {
            int t = __shfl_up_sync(0xffffffffu, kincl, o);
            if (lane >= o) kincl += t;
        }
        __syncthreads();
        if (lane == 31) wsum[wid] = kincl;
        __syncthreads();
        if (wid == 0) {
            int v = wsum[lane];
            int inc2 = v;
            #pragma unroll
            for (int o = 1; o < 32; o <<= 1) {
                int t = __shfl_up_sync(0xffffffffu, inc2, o);
                if (lane >= o) inc2 += t;
            }
            wsex[lane] = inc2 - v;
        }
        __syncthreads();
        int kr0 = wsex[wid] + (kincl - ksum);
        int kr1 = kr0 + keep0;
        if (keep0) g_live[g * kkeep + kr0] = base + n0;
        else       g_alsv[base + n0] = make_float4(MASKV, MASKV, MASKV, 0.f);
        if (keep1) g_live[g * kkeep + kr1] = base + n1;
        else       g_alsv[base + n1] = make_float4(MASKV, MASKV, MASKV, 0.f);
    }

    float t0 = keep0 ? tanhf(g_score[base + n0]) : 0.f;
    float t1 = keep1 ? tanhf(g_score[base + n1]) : 0.f;

    if (!DOFINAL) {
        g_nmask[base + n0] = keep0;
        g_nmask[base + n1] = keep1;
        float2* xr0 = (float2*)(x + (size_t)(base + n0) * F);
        float2* xr1 = (float2*)(x + (size_t)(base + n1) * F);
        for (int i = 0; i < F2; ++i) { float2 v = xr0[i]; v.x *= t0; v.y *= t0; xr0[i] = v; }
        for (int i = 0; i < F2; ++i) { float2 v = xr1[i]; v.x *= t1; v.y *= t1; xr1[i] = v; }
    } else {
        // fused mean + log_softmax: accumulate scaled rows, no global writes
        float acc[NCLS];
        #pragma unroll
        for (int c = 0; c < NCLS; ++c) acc[c] = 0.f;
        const float2* xr0 = (const float2*)(x + (size_t)(base + n0) * F);
        const float2* xr1 = (const float2*)(x + (size_t)(base + n1) * F);
        #pragma unroll
        for (int i = 0; i < NCLS / 2; ++i) {
            float2 v0 = xr0[i], v1 = xr1[i];
            acc[2 * i]     += v0.x * t0 + v1.x * t1;
            acc[2 * i + 1] += v0.y * t0 + v1.y * t1;
        }
        #pragma unroll
        for (int o = 16; o; o >>= 1)
            #pragma unroll
            for (int c = 0; c < NCLS; ++c)
                acc[c] += __shfl_down_sync(0xffffffffu, acc[c], o);
        if (lane == 0)
            #pragma unroll
            for (int c = 0; c < NCLS; ++c) redf[c][wid] = acc[c];
        __syncthreads();
        if (tid == 0) {
            float z[NCLS];
            #pragma unroll
            for (int c = 0; c < NCLS; ++c) {
                float s = 0.f;
                for (int w = 0; w < 32; ++w) s += redf[c][w];
                z[c] = s * (1.f / (NPERG / 4));
            }
            float mx = z[0];
            #pragma unroll
            for (int c = 1; c < NCLS; ++c) mx = fmaxf(mx, z[c]);
            float se = 0.f;
            #pragma unroll
            for (int c = 0; c < NCLS; ++c) se += expf(z[c] - mx);
            float lse = logf(se) + mx;
            #pragma unroll
            for (int c = 0; c < NCLS; ++c) out[g * NCLS + c] = z[c] - lse;
        }
    }
}

// ---------------- host orchestration ----------------
extern "C" void kernel_launch(void* const* d_in, const int* in_sizes, int n_in,
                              void* d_out, int out_size) {
    const float* x     = (const float*)d_in[0];
    const int*   ei    = (const int*)  d_in[1];
    const float* gamma = (const float*)d_in[3];
    const float* beta  = (const float*)d_in[4];
    const float* W1  = (const float*)d_in[5];
    const float* as1 = (const float*)d_in[6];
    const float* ad1 = (const float*)d_in[7];
    const float* b1  = (const float*)d_in[8];
    const float* W2  = (const float*)d_in[9];
    const float* as2 = (const float*)d_in[10];
    const float* ad2 = (const float*)d_in[11];
    const float* b2  = (const float*)d_in[12];
    const float* W3  = (const float*)d_in[13];
    const float* as3 = (const float*)d_in[14];
    const float* ad3 = (const float*)d_in[15];
    const float* b3  = (const float*)d_in[16];
    const float* W4  = (const float*)d_in[17];
    const float* as4 = (const float*)d_in[18];
    const float* ad4 = (const float*)d_in[19];
    const float* b4  = (const float*)d_in[20];
    const float* p1  = (const float*)d_in[21];
    const float* p2  = (const float*)d_in[22];

    int E = in_sizes[1] / 2;
    const int* src = ei;
    const int* dst = ei + E;
    int Etot = E + NTN;
    int eb = (Etot + 255) / 256;

    float *h, *oa, *ob;
    cudaGetSymbolAddress((void**)&h,  g_h);
    cudaGetSymbolAddress((void**)&oa, g_oa);
    cudaGetSymbolAddress((void**)&ob, g_ob);

    int lingrid4 = NTN / 32;            // conv1: warp per 4 rows
    int lingrid8 = NTN / 64;            // conv2: warp per 8 rows
    int lingridL = NLIVE1 / 64;         // conv3/4: live rows, warp per 8
    int gatgrid  = NTN * 32 / 256;      // warp per dst node (all nodes)
    int gatgridL = NLIVE1 * 32 / 256;   // warp per LIVE dst node

    k_stats<<<128, 128>>>(x);                                      // 0
    k_deg_bnc<<<eb + 1, 256>>>(dst, E, Etot, gamma, beta);         // 1
    k_scan_block<<<256, 256>>>();                                  // 2
    k_lin<NFEAT, 3, 16, 4, true, false><<<lingrid4, 256>>>(x, W1, as1, ad1, h); // 3 <- ncu
    k_scan_add2<<<256, 256>>>(Etot);                               // 4
    k_scatter<<<eb, 256>>>(src, dst, E, Etot);                     // 5
    k_gat<3, 16, false, 1, false><<<gatgrid, 256>>>(h, b1, oa);    // 6

    k_lin<48, 3, 16, 8, false, false><<<lingrid8, 256>>>(oa, W2, as2, ad2, h);
    k_gat<3, 16, false, 1, false><<<gatgrid, 256>>>(h, b2, ob);
    k_topk<false><<<NBATCH, 1024>>>(ob, p1, 48, NPERG / 2, 1, nullptr);
    k_lin<48, 2, 16, 8, false, true><<<lingridL, 256>>>(ob, W3, as3, ad3, h);
    k_gat<2, 16, true, 2, true><<<gatgridL, 256>>>(h, b3, oa);
    k_lin<32, 1, 10, 8, false, true><<<lingridL, 256>>>(oa, W4, as4, ad4, h);
    k_gat<1, 10, true, 4, true><<<gatgridL, 256>>>(h, b4, ob);
    k_topk<true><<<NBATCH, 1024>>>(ob, p2, 10, NPERG / 4, 0, (float*)d_out);
}